// round 10
// baseline (speedup 1.0000x reference)
#include <cuda_runtime.h>
#include <math.h>

#define BB 2
#define LL 1024
#define DD 1024
#define NN 16
#define RR 64

// scratch (no device allocations allowed)
__device__ float g_delta[BB * LL * DD];
__device__ float g_Bt[BB * LL * NN];
__device__ float g_Ct[BB * LL * NN];

// ---------------------------------------------------------------------------
// Producer (R9 verbatim): one warp per output row m.
// ---------------------------------------------------------------------------
__global__ void __launch_bounds__(64) producer_k(
    const float* __restrict__ x,   // [2048, 1024]
    const float* __restrict__ W1,  // [1024, 64]
    const float* __restrict__ WB,  // [1024, 16]
    const float* __restrict__ WC,  // [1024, 16]
    const float* __restrict__ W2)  // [64, 1024]
{
    __shared__ float xs[2][1024];
    __shared__ float ts[2][64];

    int lane = threadIdx.x & 31;
    int w = threadIdx.x >> 5;            // 0..1
    int m = blockIdx.x * 2 + w;          // row 0..2047

    const float4* xrow = (const float4*)(x + (size_t)m * 1024);
    float4* xsv = (float4*)xs[w];
#pragma unroll
    for (int i = 0; i < 8; ++i)
        xsv[lane + 32 * i] = xrow[lane + 32 * i];
    __syncwarp();

    if (lane < 16) {
        float ax = 0.f, ay = 0.f, az = 0.f, aw = 0.f;
        const float4* w1p = (const float4*)W1 + lane;
        for (int k = 0; k < 1024; ++k) {
            float a = xs[w][k];
            float4 wv = w1p[(size_t)k * 16];
            ax = fmaf(a, wv.x, ax);
            ay = fmaf(a, wv.y, ay);
            az = fmaf(a, wv.z, az);
            aw = fmaf(a, wv.w, aw);
        }
        float4 r; r.x = ax; r.y = ay; r.z = az; r.w = aw;
        ((float4*)ts[w])[lane] = r;
    } else if (lane < 24) {
        int j = lane - 16;
        float bx = 0.f, by = 0.f;
        const float2* wbp = (const float2*)WB + j;
        for (int k = 0; k < 1024; ++k) {
            float a = xs[w][k];
            float2 wv = wbp[(size_t)k * 8];
            bx = fmaf(a, wv.x, bx);
            by = fmaf(a, wv.y, by);
        }
        float2 r; r.x = bx; r.y = by;
        ((float2*)(g_Bt + (size_t)m * 16))[j] = r;
    } else {
        int j = lane - 24;
        float cx = 0.f, cy = 0.f;
        const float2* wcp = (const float2*)WC + j;
        for (int k = 0; k < 1024; ++k) {
            float a = xs[w][k];
            float2 wv = wcp[(size_t)k * 8];
            cx = fmaf(a, wv.x, cx);
            cy = fmaf(a, wv.y, cy);
        }
        float2 r; r.x = cx; r.y = cy;
        ((float2*)(g_Ct + (size_t)m * 16))[j] = r;
    }
    __syncwarp();

#pragma unroll 1
    for (int cb = 0; cb < 8; ++cb) {
        int n = cb * 128 + lane * 4;
        float ax = 0.f, ay = 0.f, az = 0.f, aw = 0.f;
        const float4* w2p = (const float4*)(W2 + n);
#pragma unroll
        for (int k = 0; k < 64; ++k) {
            float a = ts[w][k];
            float4 wv = w2p[(size_t)k * 256];
            ax = fmaf(a, wv.x, ax);
            ay = fmaf(a, wv.y, ay);
            az = fmaf(a, wv.z, az);
            aw = fmaf(a, wv.w, aw);
        }
        float4 r;
        r.x = fmaxf(ax, 0.f) + log1pf(expf(-fabsf(ax)));
        r.y = fmaxf(ay, 0.f) + log1pf(expf(-fabsf(ay)));
        r.z = fmaxf(az, 0.f) + log1pf(expf(-fabsf(az)));
        r.w = fmaxf(aw, 0.f) + log1pf(expf(-fabsf(aw)));
        *((float4*)(g_delta + (size_t)m * 1024 + n)) = r;
    }
}

// ---------------- sequential resonance scan: mirrored-lane TLP boost --------
// 2048 warps: each warp runs ONE (b,d) group in lanes 0..15 and an exact
// mirror of it in lanes 16..31 (duplicates; never written). Doubles the
// number of independent warp streams per SMSP (2 -> ~3.5) to hide the
// dependent transcendental-chain stalls. Per-lane FP sequence and the
// 16-lane shfl reduction tree are unchanged => y is bit-identical.
__global__ void __launch_bounds__(128, 4) scan_k(
    const float* __restrict__ x, const float* __restrict__ A_log,
    const float* __restrict__ Dskip, float* __restrict__ y)
{
    int lane = threadIdx.x & 31;
    int g = blockIdx.x * 4 + (threadIdx.x >> 5);   // group 0..2047
    int b = g >> 10;                               // 0..1
    int d = g & 1023;
    int n = lane & 15;                             // lanes 16..31 mirror 0..15

    float An = expf(A_log[n]);
    float phi = (float)n * 0.39269908169872414f;
    float sphi, cphi;
    sincosf(phi, &sphi, &cphi);
    float hx = __fmul_rn(0.01f, cphi), hy = __fmul_rn(0.01f, sphi);
    float dsk = Dskip[d];

    size_t rowbase = ((size_t)b * LL) * DD + d;
    const float* xp = x + rowbase;
    const float* dp = g_delta + rowbase;
    const float* bp = g_Bt + ((size_t)b * LL) * NN + n;
    const float* cp = g_Ct + ((size_t)b * LL) * NN + n;
    float* yp = y + rowbase;

    float xv = __ldg(xp);
    float dv = __ldg(dp);
    float bn = __ldg(bp);
    float cn = __ldg(cp);

#pragma unroll 2
    for (int t = 0; t < LL; ++t) {
        int tn = (t < LL - 1) ? (t + 1) : t;
        float xv2 = __ldg(xp + (size_t)tn * DD);
        float dv2 = __ldg(dp + (size_t)tn * DD);
        float bn2 = __ldg(bp + tn * NN);
        float cn2 = __ldg(cp + tn * NN);

        // ---- fractal_compress(h, e) ----
        float mag = __fsqrt_rn(__fadd_rn(__fadd_rn(__fmul_rn(hx, hx), __fmul_rn(hy, hy)), 1e-8f));
        float ph  = atan2f(hy, __fadd_rn(hx, 1e-10f));
        float e   = __fadd_rn(1.0f, __fmul_rn(dv, An));
        float cm  = fminf(expf(__fmul_rn(e, logf(__fadd_rn(mag, 1e-8f)))), 10.0f);
        float sph, cph;
        sincosf(ph, &sph, &cph);
        float hcx = __fmul_rn(cm, cph);
        float hcy = __fmul_rn(cm, sph);

        // ---- injection on carrier phases ----
        float u   = __fmul_rn(xv, bn);
        float ijx = __fmul_rn(u, cphi);
        float ijy = __fmul_rn(u, sphi);

        // ---- resonance gate: gamma = 0.5 * cos((pa-pb)/2)^2 ----
        float pa = atan2f(ijy, __fadd_rn(ijx, 1e-10f));
        float pb = atan2f(hcy, __fadd_rn(hcx, 1e-10f));
        float cd = cosf(__fmul_rn(__fsub_rn(pa, pb), 0.5f));
        float gam = __fmul_rn(0.5f, __fmul_rn(cd, cd));

        // ---- inject + mag_squash ----
        float sx = __fadd_rn(hcx, __fmul_rn(gam, ijx));
        float sy = __fadd_rn(hcy, __fmul_rn(gam, ijy));
        float sm = __fsqrt_rn(__fadd_rn(__fadd_rn(__fmul_rn(sx, sx), __fmul_rn(sy, sy)), 1e-8f));
        float ps = atan2f(sy, __fadd_rn(sx, 1e-10f));
        float th = tanhf(sm);
        float sps, cps;
        sincosf(ps, &sps, &cps);
        hx = __fmul_rn(th, cps);
        hy = __fmul_rn(th, sps);

        // ---- readout (tree confined to each 16-lane half; halves identical) --
        float v = __fmul_rn(hx, cn);
        v += __shfl_xor_sync(0xffffffffu, v, 8);
        v += __shfl_xor_sync(0xffffffffu, v, 4);
        v += __shfl_xor_sync(0xffffffffu, v, 2);
        v += __shfl_xor_sync(0xffffffffu, v, 1);
        if (lane == 0) yp[(size_t)t * DD] = __fadd_rn(__fmul_rn(xv, dsk), v);

        xv = xv2; dv = dv2; bn = bn2; cn = cn2;
    }
}

extern "C" void kernel_launch(void* const* d_in, const int* in_sizes, int n_in,
                              void* d_out, int out_size)
{
    const float *x = 0, *A_log = 0, *W_dt1 = 0, *W_dt2 = 0, *W_B = 0, *W_C = 0, *Dskip = 0;
    for (int i = 0; i < n_in; ++i) {
        const float* p = (const float*)d_in[i];
        int s = in_sizes[i];
        if (s == BB * LL * DD)      { if (!x) x = p; }
        else if (s == NN)           { if (!A_log) A_log = p; }
        else if (s == DD * RR)      { if (!W_dt1) W_dt1 = p; else W_dt2 = p; }
        else if (s == DD * NN)      { if (!W_B) W_B = p; else W_C = p; }
        else if (s == DD)           { if (!Dskip) Dskip = p; }
    }
    float* y = (float*)d_out;

    // producer: Bt, Ct, delta (bit-identical chains, warp-per-row)
    producer_k<<<1024, 64>>>(x, W_dt1, W_B, W_C, W_dt2);
    // scan: 2048 mirrored-lane warps (512 blocks x 4 warps) for stall hiding
    scan_k<<<512, 128>>>(x, A_log, Dskip, y);
}

// round 11
// speedup vs baseline: 1.2136x; 1.2136x over previous
#include <cuda_runtime.h>
#include <math.h>

#define BB 2
#define LL 1024
#define DD 1024
#define NN 16
#define RR 64
#define PBM 16   // producer rows per block

// scratch (no device allocations allowed)
__device__ float g_delta[BB * LL * DD];
__device__ float g_Bt[BB * LL * NN];
__device__ float g_Ct[BB * LL * NN];

// ---------------------------------------------------------------------------
// Producer: register-tiled fused GEMM.
//   Phase 1: C1[16,96] = x_tile[16,1024] @ [W1|WB|WC]   (2 rows x 3 cols/thread)
//   Phase 2: delta[16,1024] = softplus(tmp[16,64] @ W2) (4 cols x 16 rows/thread)
// Every output is a single-accumulator, k-ascending fmaf chain with the
// identical softplus => bit-identical delta/Bt/Ct to the passing kernel.
// ---------------------------------------------------------------------------
__global__ void __launch_bounds__(256) producer_k(
    const float* __restrict__ x,   // [2048, 1024]
    const float* __restrict__ W1,  // [1024, 64]
    const float* __restrict__ WB,  // [1024, 16]
    const float* __restrict__ WC,  // [1024, 16]
    const float* __restrict__ W2)  // [64, 1024]
{
    __shared__ float As[PBM][64];   // x k-chunk tile       (4 KB)
    __shared__ float Ws[64][96];    // [W1|WB|WC] k-chunk   (24 KB)
    __shared__ float Ts[PBM][64];   // tmp rows             (4 KB)

    int tid = threadIdx.x;
    int m0 = blockIdx.x * PBM;

    int tc = tid & 31;              // cols: tc, tc+32, tc+64
    int tr = (tid >> 5) * 2;        // rows: tr, tr+1

    float a00 = 0.f, a01 = 0.f, a02 = 0.f;
    float a10 = 0.f, a11 = 0.f, a12 = 0.f;

    for (int k0 = 0; k0 < 1024; k0 += 64) {
        __syncthreads();
        // stage x tile 16x64 (one float4 per thread)
        {
            int r = tid >> 4, c = (tid & 15) * 4;
            *(float4*)&As[r][c] = *(const float4*)&x[(size_t)(m0 + r) * 1024 + k0 + c];
        }
        // stage W1 chunk 64x64 -> Ws[:, 0:64] (4 float4 per thread)
#pragma unroll
        for (int j = 0; j < 4; ++j) {
            int idx = (tid + j * 256) * 4;
            int r = idx >> 6, c = idx & 63;
            *(float4*)&Ws[r][c] = *(const float4*)&W1[(size_t)(k0 + r) * 64 + c];
        }
        // stage WB -> Ws[:, 64:80], WC -> Ws[:, 80:96] (one float4 each)
        {
            int r = tid >> 2, c = (tid & 3) * 4;
            *(float4*)&Ws[r][64 + c] = *(const float4*)&WB[(size_t)(k0 + r) * 16 + c];
            *(float4*)&Ws[r][80 + c] = *(const float4*)&WC[(size_t)(k0 + r) * 16 + c];
        }
        __syncthreads();

#pragma unroll
        for (int k = 0; k < 64; ++k) {
            float w0 = Ws[k][tc], w1 = Ws[k][tc + 32], w2 = Ws[k][tc + 64];
            float a0 = As[tr][k], a1 = As[tr + 1][k];
            a00 = fmaf(a0, w0, a00);
            a01 = fmaf(a0, w1, a01);
            a02 = fmaf(a0, w2, a02);
            a10 = fmaf(a1, w0, a10);
            a11 = fmaf(a1, w1, a11);
            a12 = fmaf(a1, w2, a12);
        }
    }

    // write Bt/Ct (col tc+64 of C1), park tmp cols in smem
    if (tc < 16) {
        g_Bt[(size_t)(m0 + tr) * 16 + tc]     = a02;
        g_Bt[(size_t)(m0 + tr + 1) * 16 + tc] = a12;
    } else {
        g_Ct[(size_t)(m0 + tr) * 16 + (tc - 16)]     = a02;
        g_Ct[(size_t)(m0 + tr + 1) * 16 + (tc - 16)] = a12;
    }
    __syncthreads();   // before overwriting nothing, but order Ts writes vs reads
    Ts[tr][tc]          = a00;
    Ts[tr][tc + 32]     = a01;
    Ts[tr + 1][tc]      = a10;
    Ts[tr + 1][tc + 32] = a11;
    __syncthreads();

    // delta phase: thread -> 4 consecutive cols, all 16 rows
    int c0 = tid * 4;
    float4 acc[PBM];
#pragma unroll
    for (int r = 0; r < PBM; ++r) { acc[r].x = 0.f; acc[r].y = 0.f; acc[r].z = 0.f; acc[r].w = 0.f; }

#pragma unroll 4
    for (int k = 0; k < 64; ++k) {
        float4 w = *(const float4*)&W2[(size_t)k * 1024 + c0];
#pragma unroll
        for (int r = 0; r < PBM; ++r) {
            float t = Ts[r][k];
            acc[r].x = fmaf(t, w.x, acc[r].x);
            acc[r].y = fmaf(t, w.y, acc[r].y);
            acc[r].z = fmaf(t, w.z, acc[r].z);
            acc[r].w = fmaf(t, w.w, acc[r].w);
        }
    }

#pragma unroll
    for (int r = 0; r < PBM; ++r) {
        float4 v;
        v.x = fmaxf(acc[r].x, 0.f) + log1pf(expf(-fabsf(acc[r].x)));
        v.y = fmaxf(acc[r].y, 0.f) + log1pf(expf(-fabsf(acc[r].y)));
        v.z = fmaxf(acc[r].z, 0.f) + log1pf(expf(-fabsf(acc[r].z)));
        v.w = fmaxf(acc[r].w, 0.f) + log1pf(expf(-fabsf(acc[r].w)));
        *(float4*)&g_delta[(size_t)(m0 + r) * 1024 + c0] = v;
    }
}

// ---------------- sequential resonance scan (R5 verbatim — latency floor) ---
__global__ void __launch_bounds__(256, 1) scan_k(
    const float* __restrict__ x, const float* __restrict__ A_log,
    const float* __restrict__ Dskip, float* __restrict__ y)
{
    int tid = threadIdx.x;
    int bid = blockIdx.x;                 // 0..127
    int b = bid >> 6;                     // 0..1
    int d = ((bid & 63) << 4) | (tid >> 4);
    int n = tid & 15;

    float An = expf(A_log[n]);
    float phi = (float)n * 0.39269908169872414f;
    float sphi, cphi;
    sincosf(phi, &sphi, &cphi);
    float hx = __fmul_rn(0.01f, cphi), hy = __fmul_rn(0.01f, sphi);
    float dsk = Dskip[d];

    size_t rowbase = ((size_t)b * LL) * DD + d;
    const float* xp = x + rowbase;
    const float* dp = g_delta + rowbase;
    const float* bp = g_Bt + ((size_t)b * LL) * NN + n;
    const float* cp = g_Ct + ((size_t)b * LL) * NN + n;
    float* yp = y + rowbase;

    float xv = __ldg(xp);
    float dv = __ldg(dp);
    float bn = __ldg(bp);
    float cn = __ldg(cp);

#pragma unroll 2
    for (int t = 0; t < LL; ++t) {
        int tn = (t < LL - 1) ? (t + 1) : t;
        float xv2 = __ldg(xp + (size_t)tn * DD);
        float dv2 = __ldg(dp + (size_t)tn * DD);
        float bn2 = __ldg(bp + tn * NN);
        float cn2 = __ldg(cp + tn * NN);

        // ---- fractal_compress(h, e) ----
        float mag = __fsqrt_rn(__fadd_rn(__fadd_rn(__fmul_rn(hx, hx), __fmul_rn(hy, hy)), 1e-8f));
        float ph  = atan2f(hy, __fadd_rn(hx, 1e-10f));
        float e   = __fadd_rn(1.0f, __fmul_rn(dv, An));
        float cm  = fminf(expf(__fmul_rn(e, logf(__fadd_rn(mag, 1e-8f)))), 10.0f);
        float sph, cph;
        sincosf(ph, &sph, &cph);
        float hcx = __fmul_rn(cm, cph);
        float hcy = __fmul_rn(cm, sph);

        // ---- injection on carrier phases ----
        float u   = __fmul_rn(xv, bn);
        float ijx = __fmul_rn(u, cphi);
        float ijy = __fmul_rn(u, sphi);

        // ---- resonance gate: gamma = 0.5 * cos((pa-pb)/2)^2 ----
        float pa = atan2f(ijy, __fadd_rn(ijx, 1e-10f));
        float pb = atan2f(hcy, __fadd_rn(hcx, 1e-10f));
        float cd = cosf(__fmul_rn(__fsub_rn(pa, pb), 0.5f));
        float gam = __fmul_rn(0.5f, __fmul_rn(cd, cd));

        // ---- inject + mag_squash ----
        float sx = __fadd_rn(hcx, __fmul_rn(gam, ijx));
        float sy = __fadd_rn(hcy, __fmul_rn(gam, ijy));
        float sm = __fsqrt_rn(__fadd_rn(__fadd_rn(__fmul_rn(sx, sx), __fmul_rn(sy, sy)), 1e-8f));
        float ps = atan2f(sy, __fadd_rn(sx, 1e-10f));
        float th = tanhf(sm);
        float sps, cps;
        sincosf(ps, &sps, &cps);
        hx = __fmul_rn(th, cps);
        hy = __fmul_rn(th, sps);

        // ---- readout ----
        float v = __fmul_rn(hx, cn);
        v += __shfl_xor_sync(0xffffffffu, v, 8);
        v += __shfl_xor_sync(0xffffffffu, v, 4);
        v += __shfl_xor_sync(0xffffffffu, v, 2);
        v += __shfl_xor_sync(0xffffffffu, v, 1);
        if (n == 0) yp[(size_t)t * DD] = __fadd_rn(__fmul_rn(xv, dsk), v);

        xv = xv2; dv = dv2; bn = bn2; cn = cn2;
    }
}

extern "C" void kernel_launch(void* const* d_in, const int* in_sizes, int n_in,
                              void* d_out, int out_size)
{
    const float *x = 0, *A_log = 0, *W_dt1 = 0, *W_dt2 = 0, *W_B = 0, *W_C = 0, *Dskip = 0;
    for (int i = 0; i < n_in; ++i) {
        const float* p = (const float*)d_in[i];
        int s = in_sizes[i];
        if (s == BB * LL * DD)      { if (!x) x = p; }
        else if (s == NN)           { if (!A_log) A_log = p; }
        else if (s == DD * RR)      { if (!W_dt1) W_dt1 = p; else W_dt2 = p; }
        else if (s == DD * NN)      { if (!W_B) W_B = p; else W_C = p; }
        else if (s == DD)           { if (!Dskip) Dskip = p; }
    }
    float* y = (float*)d_out;

    // register-tiled fused producer: Bt, Ct, delta (bit-identical chains)
    producer_k<<<BB * LL / PBM, 256>>>(x, W_dt1, W_B, W_C, W_dt2);
    // sequential scan (R5 verbatim — per-warp serial latency floor)
    scan_k<<<128, 256>>>(x, A_log, Dskip, y);
}

// round 12
// speedup vs baseline: 1.2325x; 1.0156x over previous
#include <cuda_runtime.h>
#include <math.h>

#define BB 2
#define LL 1024
#define DD 1024
#define NN 16
#define RR 64
#define PBM 8    // producer rows per block -> grid 256 (no idle SMs)

// scratch (no device allocations allowed)
__device__ float g_delta[BB * LL * DD];
__device__ float g_Bt[BB * LL * NN];
__device__ float g_Ct[BB * LL * NN];

// ---------------------------------------------------------------------------
// Producer: register-tiled fused GEMM, occupancy-tuned.
//   Phase 1: C1[8,96] = x_tile[8,1024] @ [W1|WB|WC]   (1 row x 3 cols/thread)
//   Phase 2: delta[8,1024] = softplus(tmp[8,64] @ W2) (4 cols x 8 rows/thread)
// Every output is a single-accumulator, k-ascending fmaf chain with the
// identical softplus => bit-identical delta/Bt/Ct to the passing kernel.
// ---------------------------------------------------------------------------
__global__ void __launch_bounds__(256) producer_k(
    const float* __restrict__ x,   // [2048, 1024]
    const float* __restrict__ W1,  // [1024, 64]
    const float* __restrict__ WB,  // [1024, 16]
    const float* __restrict__ WC,  // [1024, 16]
    const float* __restrict__ W2)  // [64, 1024]
{
    __shared__ float As[PBM][64];   // x k-chunk tile       (2 KB)
    __shared__ float Ws[64][96];    // [W1|WB|WC] k-chunk   (24 KB)
    __shared__ float Ts[PBM][64];   // tmp rows             (2 KB)

    int tid = threadIdx.x;
    int m0 = blockIdx.x * PBM;

    int tc = tid & 31;              // cols: tc, tc+32, tc+64
    int tr = tid >> 5;              // row 0..7

    float a0 = 0.f, a1 = 0.f, a2 = 0.f;

    for (int k0 = 0; k0 < 1024; k0 += 64) {
        __syncthreads();
        // stage x tile 8x64 (threads 0..127, one float4 each)
        if (tid < 128) {
            int r = tid >> 4, c = (tid & 15) * 4;
            *(float4*)&As[r][c] = *(const float4*)&x[(size_t)(m0 + r) * 1024 + k0 + c];
        }
        // stage W1 chunk 64x64 -> Ws[:, 0:64] (4 float4 per thread)
#pragma unroll
        for (int j = 0; j < 4; ++j) {
            int idx = (tid + j * 256) * 4;
            int r = idx >> 6, c = idx & 63;
            *(float4*)&Ws[r][c] = *(const float4*)&W1[(size_t)(k0 + r) * 64 + c];
        }
        // stage WB -> Ws[:, 64:80], WC -> Ws[:, 80:96] (one float4 each)
        {
            int r = tid >> 2, c = (tid & 3) * 4;
            *(float4*)&Ws[r][64 + c] = *(const float4*)&WB[(size_t)(k0 + r) * 16 + c];
            *(float4*)&Ws[r][80 + c] = *(const float4*)&WC[(size_t)(k0 + r) * 16 + c];
        }
        __syncthreads();

#pragma unroll
        for (int k = 0; k < 64; ++k) {
            float a = As[tr][k];
            a0 = fmaf(a, Ws[k][tc],      a0);
            a1 = fmaf(a, Ws[k][tc + 32], a1);
            a2 = fmaf(a, Ws[k][tc + 64], a2);
        }
    }

    // write Bt/Ct (col tc+64 of C1), park tmp cols in smem
    if (tc < 16) {
        g_Bt[(size_t)(m0 + tr) * 16 + tc] = a2;
    } else {
        g_Ct[(size_t)(m0 + tr) * 16 + (tc - 16)] = a2;
    }
    __syncthreads();
    Ts[tr][tc]      = a0;
    Ts[tr][tc + 32] = a1;
    __syncthreads();

    // delta phase: thread -> 4 consecutive cols, all 8 rows
    int c0 = tid * 4;
    float4 acc[PBM];
#pragma unroll
    for (int r = 0; r < PBM; ++r) { acc[r].x = 0.f; acc[r].y = 0.f; acc[r].z = 0.f; acc[r].w = 0.f; }

#pragma unroll 4
    for (int k = 0; k < 64; ++k) {
        float4 w = *(const float4*)&W2[(size_t)k * 1024 + c0];
#pragma unroll
        for (int r = 0; r < PBM; ++r) {
            float t = Ts[r][k];
            acc[r].x = fmaf(t, w.x, acc[r].x);
            acc[r].y = fmaf(t, w.y, acc[r].y);
            acc[r].z = fmaf(t, w.z, acc[r].z);
            acc[r].w = fmaf(t, w.w, acc[r].w);
        }
    }

#pragma unroll
    for (int r = 0; r < PBM; ++r) {
        float4 v;
        v.x = fmaxf(acc[r].x, 0.f) + log1pf(expf(-fabsf(acc[r].x)));
        v.y = fmaxf(acc[r].y, 0.f) + log1pf(expf(-fabsf(acc[r].y)));
        v.z = fmaxf(acc[r].z, 0.f) + log1pf(expf(-fabsf(acc[r].z)));
        v.w = fmaxf(acc[r].w, 0.f) + log1pf(expf(-fabsf(acc[r].w)));
        *(float4*)&g_delta[(size_t)(m0 + r) * 1024 + c0] = v;
    }
}

// ---------------- sequential resonance scan (R5 verbatim — latency floor) ---
__global__ void __launch_bounds__(256, 1) scan_k(
    const float* __restrict__ x, const float* __restrict__ A_log,
    const float* __restrict__ Dskip, float* __restrict__ y)
{
    int tid = threadIdx.x;
    int bid = blockIdx.x;                 // 0..127
    int b = bid >> 6;                     // 0..1
    int d = ((bid & 63) << 4) | (tid >> 4);
    int n = tid & 15;

    float An = expf(A_log[n]);
    float phi = (float)n * 0.39269908169872414f;
    float sphi, cphi;
    sincosf(phi, &sphi, &cphi);
    float hx = __fmul_rn(0.01f, cphi), hy = __fmul_rn(0.01f, sphi);
    float dsk = Dskip[d];

    size_t rowbase = ((size_t)b * LL) * DD + d;
    const float* xp = x + rowbase;
    const float* dp = g_delta + rowbase;
    const float* bp = g_Bt + ((size_t)b * LL) * NN + n;
    const float* cp = g_Ct + ((size_t)b * LL) * NN + n;
    float* yp = y + rowbase;

    float xv = __ldg(xp);
    float dv = __ldg(dp);
    float bn = __ldg(bp);
    float cn = __ldg(cp);

#pragma unroll 2
    for (int t = 0; t < LL; ++t) {
        int tn = (t < LL - 1) ? (t + 1) : t;
        float xv2 = __ldg(xp + (size_t)tn * DD);
        float dv2 = __ldg(dp + (size_t)tn * DD);
        float bn2 = __ldg(bp + tn * NN);
        float cn2 = __ldg(cp + tn * NN);

        // ---- fractal_compress(h, e) ----
        float mag = __fsqrt_rn(__fadd_rn(__fadd_rn(__fmul_rn(hx, hx), __fmul_rn(hy, hy)), 1e-8f));
        float ph  = atan2f(hy, __fadd_rn(hx, 1e-10f));
        float e   = __fadd_rn(1.0f, __fmul_rn(dv, An));
        float cm  = fminf(expf(__fmul_rn(e, logf(__fadd_rn(mag, 1e-8f)))), 10.0f);
        float sph, cph;
        sincosf(ph, &sph, &cph);
        float hcx = __fmul_rn(cm, cph);
        float hcy = __fmul_rn(cm, sph);

        // ---- injection on carrier phases ----
        float u   = __fmul_rn(xv, bn);
        float ijx = __fmul_rn(u, cphi);
        float ijy = __fmul_rn(u, sphi);

        // ---- resonance gate: gamma = 0.5 * cos((pa-pb)/2)^2 ----
        float pa = atan2f(ijy, __fadd_rn(ijx, 1e-10f));
        float pb = atan2f(hcy, __fadd_rn(hcx, 1e-10f));
        float cd = cosf(__fmul_rn(__fsub_rn(pa, pb), 0.5f));
        float gam = __fmul_rn(0.5f, __fmul_rn(cd, cd));

        // ---- inject + mag_squash ----
        float sx = __fadd_rn(hcx, __fmul_rn(gam, ijx));
        float sy = __fadd_rn(hcy, __fmul_rn(gam, ijy));
        float sm = __fsqrt_rn(__fadd_rn(__fadd_rn(__fmul_rn(sx, sx), __fmul_rn(sy, sy)), 1e-8f));
        float ps = atan2f(sy, __fadd_rn(sx, 1e-10f));
        float th = tanhf(sm);
        float sps, cps;
        sincosf(ps, &sps, &cps);
        hx = __fmul_rn(th, cps);
        hy = __fmul_rn(th, sps);

        // ---- readout ----
        float v = __fmul_rn(hx, cn);
        v += __shfl_xor_sync(0xffffffffu, v, 8);
        v += __shfl_xor_sync(0xffffffffu, v, 4);
        v += __shfl_xor_sync(0xffffffffu, v, 2);
        v += __shfl_xor_sync(0xffffffffu, v, 1);
        if (n == 0) yp[(size_t)t * DD] = __fadd_rn(__fmul_rn(xv, dsk), v);

        xv = xv2; dv = dv2; bn = bn2; cn = cn2;
    }
}

extern "C" void kernel_launch(void* const* d_in, const int* in_sizes, int n_in,
                              void* d_out, int out_size)
{
    const float *x = 0, *A_log = 0, *W_dt1 = 0, *W_dt2 = 0, *W_B = 0, *W_C = 0, *Dskip = 0;
    for (int i = 0; i < n_in; ++i) {
        const float* p = (const float*)d_in[i];
        int s = in_sizes[i];
        if (s == BB * LL * DD)      { if (!x) x = p; }
        else if (s == NN)           { if (!A_log) A_log = p; }
        else if (s == DD * RR)      { if (!W_dt1) W_dt1 = p; else W_dt2 = p; }
        else if (s == DD * NN)      { if (!W_B) W_B = p; else W_C = p; }
        else if (s == DD)           { if (!Dskip) Dskip = p; }
    }
    float* y = (float*)d_out;

    // register-tiled fused producer: Bt, Ct, delta (bit-identical chains)
    producer_k<<<BB * LL / PBM, 256>>>(x, W_dt1, W_B, W_C, W_dt2);
    // sequential scan (R5 verbatim — per-warp serial latency floor)
    scan_k<<<128, 256>>>(x, A_log, Dskip, y);
}